// round 14
// baseline (speedup 1.0000x reference)
#include <cuda_runtime.h>
#include <cuda_fp16.h>
#include <cstdint>
#include <cstddef>

// ---------------------------------------------------------------------------
// LSTM: x[256,512,512] -> LSTM(H=1024), last hidden -> FC(512). out fp32.
// dummy (shifts ncu capture slot onto rec) -> prep -> xproj (R7-proven)
//   -> persistent recurrence (W_hh smem-stationary, 3-stage cp.async ring,
//      ONE sync/chunk, dedicated zs, c in regs, xW prefetch under barrier)
//   -> fp32 FC
// tcgen05 unavailable: harness compiles PTX at compute_103 (no 'a' features).
// ---------------------------------------------------------------------------

#define DEVFN __device__ __forceinline__

// ------------------------- static device scratch ---------------------------
__device__ __half  g_x[67108864];        // x fp16 [b*512+t][512]
__device__ __half  g_Wih[2097152];       // W_ih fp16 [4096][512]
__device__ __half  g_Whh[4194304];       // W_hh fp16 [4096][1024]
__device__ float   g_bias[4096];         // b_ih + b_hh
__device__ float   g_xwi[134217728];     // per-gate xW fp32 [t][b][1024]
__device__ float   g_xwf[134217728];
__device__ float   g_xwg[134217728];
__device__ float   g_xwo[134217728];
__device__ __half  g_h[2 * 262144];      // double-buffered hidden fp16 [b][1024]
__device__ float   g_hT[262144];         // final hidden fp32
__device__ unsigned g_bar;               // grid barrier (monotonic)

// ------------------------------ helpers ------------------------------------
DEVFN void ldmx4(unsigned &r0, unsigned &r1, unsigned &r2, unsigned &r3,
                 const void* p) {
    unsigned a = (unsigned)__cvta_generic_to_shared(p);
    asm volatile("ldmatrix.sync.aligned.m8n8.x4.shared.b16 {%0,%1,%2,%3}, [%4];"
                 : "=r"(r0), "=r"(r1), "=r"(r2), "=r"(r3) : "r"(a));
}

DEVFN void mma16816(float* c, const unsigned* a, const unsigned* b) {
    asm volatile(
        "mma.sync.aligned.m16n8k16.row.col.f32.f16.f16.f32 "
        "{%0,%1,%2,%3}, {%4,%5,%6,%7}, {%8,%9}, {%0,%1,%2,%3};"
        : "+f"(c[0]), "+f"(c[1]), "+f"(c[2]), "+f"(c[3])
        : "r"(a[0]), "r"(a[1]), "r"(a[2]), "r"(a[3]), "r"(b[0]), "r"(b[1]));
}

// cp.async 16B, L2-only (.cg) — required for cross-SM h coherence
DEVFN void cpa16(void* smem, const void* gmem) {
    unsigned a = (unsigned)__cvta_generic_to_shared(smem);
    asm volatile("cp.async.cg.shared.global [%0], [%1], 16;" :: "r"(a), "l"(gmem));
}
DEVFN void cpcommit() { asm volatile("cp.async.commit_group;"); }
template <int N> DEVFN void cpwait() {
    asm volatile("cp.async.wait_group %0;" :: "n"(N));
}

DEVFN float fsig(float x)  { return 1.f / (1.f + __expf(-x)); }
DEVFN float ftanh(float x) { return 1.f - 2.f / (__expf(2.f * x) + 1.f); }

// ------------------------------ dummy kernel -------------------------------
// Launch-slot shim: shifts the harness's fixed ncu capture slot (-s 5 -c 1)
// from fc_kernel onto lstm_rec_kernel so the recurrence finally gets profiled.
__global__ void dummy_kernel() {}

// ------------------------------- prep kernel -------------------------------
__global__ void prep_kernel(const float* __restrict__ x,
                            const float* __restrict__ Wih,
                            const float* __restrict__ Whh,
                            const float* __restrict__ bih,
                            const float* __restrict__ bhh) {
    size_t i0 = (size_t)blockIdx.x * blockDim.x + threadIdx.x;
    size_t stride = (size_t)gridDim.x * blockDim.x;
    for (size_t i = i0; i < 33554432u; i += stride) {
        float2 v = ((const float2*)x)[i];
        ((__half2*)g_x)[i] = __floats2half2_rn(v.x, v.y);
    }
    for (size_t i = i0; i < 1048576u; i += stride) {
        float2 v = ((const float2*)Wih)[i];
        ((__half2*)g_Wih)[i] = __floats2half2_rn(v.x, v.y);
    }
    for (size_t i = i0; i < 2097152u; i += stride) {
        float2 v = ((const float2*)Whh)[i];
        ((__half2*)g_Whh)[i] = __floats2half2_rn(v.x, v.y);
    }
    for (size_t i = i0; i < 4096u; i += stride) g_bias[i] = bih[i] + bhh[i];
    __half2 z2 = __float2half2_rn(0.f);
    for (size_t i = i0; i < 262144u; i += stride)
        ((__half2*)g_h)[i] = z2;   // zero both 256x1024 fp16 h buffers
    if (i0 == 0) g_bar = 0u;
}

// ------------------------- phase A: x @ W_ih^T (R7-proven) -----------------
// M=131072 (b*512+t), K=512, N=4096. CTA tile 128x128, 8 warps (2m x 4n),
// warp tile 64x32. 2-stage cp.async pipeline over 8 K-chunks of 64.
#define XP_SMEM (2 * 128 * 72 * 2 * 2)
__global__ __launch_bounds__(256) void xproj_kernel() {
    extern __shared__ __align__(16) unsigned char xsm[];
    __half* xs = (__half*)xsm;                       // [2][128][72]
    __half* ws = (__half*)(xsm + 2 * 128 * 72 * 2);  // [2][128][72]
    const int tid = threadIdx.x, lane = tid & 31, warp = tid >> 5;
    const int n0 = blockIdx.x * 128, m0 = blockIdx.y * 128;
    const int wm = warp >> 2, wn = warp & 3;

    float acc[4][4][4];
#pragma unroll
    for (int a = 0; a < 4; ++a)
#pragma unroll
        for (int b = 0; b < 4; ++b)
#pragma unroll
            for (int c = 0; c < 4; ++c) acc[a][b][c] = 0.f;

    const __half* xbase = g_x + (size_t)m0 * 512;
    const __half* wbase = g_Wih + (size_t)n0 * 512;

    auto issue = [&](int kc) {
        __half* xd = xs + (kc & 1) * 9216;
        __half* wd = ws + (kc & 1) * 9216;
        const __half* xsrc = xbase + kc * 64;
        const __half* wsrc = wbase + kc * 64;
#pragma unroll
        for (int q = 0; q < 4; ++q) {
            int i = tid + q * 256;          // 0..1023
            int r = i >> 3, v = i & 7;
            cpa16(xd + r * 72 + v * 8, xsrc + (size_t)r * 512 + v * 8);
            cpa16(wd + r * 72 + v * 8, wsrc + (size_t)r * 512 + v * 8);
        }
    };

    issue(0); cpcommit();
    for (int kc = 0; kc < 8; ++kc) {
        if (kc < 7) { issue(kc + 1); cpcommit(); cpwait<1>(); }
        else        { cpwait<0>(); }
        __syncthreads();
        const __half* xb = xs + (kc & 1) * 9216;
        const __half* wb = ws + (kc & 1) * 9216;
#pragma unroll
        for (int k16 = 0; k16 < 4; ++k16) {
            const int kk = k16 * 16;
            unsigned af[4][4], bf[4][2];
#pragma unroll
            for (int ma = 0; ma < 4; ++ma)
                ldmx4(af[ma][0], af[ma][1], af[ma][2], af[ma][3],
                      xb + (wm * 64 + ma * 16 + (lane & 15)) * 72
                         + kk + (lane >> 4) * 8);
#pragma unroll
            for (int pp = 0; pp < 2; ++pp) {
                unsigned d0, d1, d2, d3;
                ldmx4(d0, d1, d2, d3,
                      wb + (wn * 32 + pp * 16 + ((lane >> 3) & 1) * 8
                            + (lane & 7)) * 72 + kk + (lane >> 4) * 8);
                bf[pp * 2 + 0][0] = d0; bf[pp * 2 + 1][0] = d1;
                bf[pp * 2 + 0][1] = d2; bf[pp * 2 + 1][1] = d3;
            }
#pragma unroll
            for (int ma = 0; ma < 4; ++ma)
#pragma unroll
                for (int na = 0; na < 4; ++na)
                    mma16816(acc[ma][na], af[ma], bf[na]);
        }
        __syncthreads();
    }

    // store fp32 xW with bias, per-gate [t][b][unit]
    const int gate = n0 >> 10;
    float* xw = (gate == 0) ? g_xwi : (gate == 1) ? g_xwf
              : (gate == 2) ? g_xwg : g_xwo;
    const int nu0 = n0 & 1023;
#pragma unroll
    for (int ma = 0; ma < 4; ++ma)
#pragma unroll
        for (int na = 0; na < 4; ++na) {
            int m  = m0 + wm * 64 + ma * 16 + (lane >> 2);
            int nu = nu0 + wn * 32 + na * 8 + ((lane & 3) << 1);
            int bb = m >> 9, tt = m & 511;
            float bs0 = g_bias[(gate << 10) + nu];
            float bs1 = g_bias[(gate << 10) + nu + 1];
            size_t o0 = ((size_t)tt * 256 + bb) * 1024 + nu;
            *(float2*)(xw + o0) =
                make_float2(acc[ma][na][0] + bs0, acc[ma][na][1] + bs1);
            size_t o1 = ((size_t)(tt + 8) * 256 + bb) * 1024 + nu;
            *(float2*)(xw + o1) =
                make_float2(acc[ma][na][2] + bs0, acc[ma][na][3] + bs1);
        }
}

// --------------------- phase B: persistent recurrence ----------------------
// 128 CTAs = 2 m-tiles(128 batch rows) x 64 n-tiles(16 units = 64 gate cols).
// Ws [64][1032] fp16 stationary; hs [3][128][72] fp16 ring, ONE sync/chunk
// (issue(kc+2) targets stage (kc-1)%3, consumption fenced by top-of-loop
// sync); zs [128][68] fp32 DEDICATED (no alias -> no pre-spill sync).
// Cell state in regs, xW prefetched per step, global monotonic barrier.
#define WS_BYTES  (64 * 1032 * 2)                  // 132096
#define HS_BYTES  (3 * 128 * 72 * 2)               // 55296
#define REC_SMEM  (WS_BYTES + HS_BYTES + 128 * 68 * 4)   // 222208 < 227KB
__global__ __launch_bounds__(256, 1) void lstm_rec_kernel() {
    extern __shared__ __align__(16) unsigned char smem_raw[];
    __half* Ws = (__half*)smem_raw;                        // [64][1032]
    __half* hs = (__half*)(smem_raw + WS_BYTES);           // [3][128][72]
    float*  zs = (float*)(smem_raw + WS_BYTES + HS_BYTES); // [128][68]

    const int tid = threadIdx.x, lane = tid & 31, warp = tid >> 5;
    const int nt = blockIdx.x & 63, mt = blockIdx.x >> 6;
    const int h0 = nt * 16, m0 = mt * 128;
    const int wm = warp >> 1, wn = warp & 1;   // warp tile 32m x 32n

    // load W_hh slice: smem row r <-> gate (r>>4), unit h0+(r&15); full K=1024
    for (int i = tid; i < 8192; i += 256) {
        int r = i >> 7, v = i & 127;
        int gr = ((r >> 4) << 10) + h0 + (r & 15);
        *(uint4*)(Ws + r * 1032 + v * 8) =
            *(const uint4*)(g_Whh + (size_t)gr * 1024 + v * 8);
    }

    const int un = (tid & 7) * 2;   // 2 adjacent units per thread
    const int rw = tid >> 3;        // row group 0..31
    float creg[4][2];
#pragma unroll
    for (int s = 0; s < 4; ++s) { creg[s][0] = 0.f; creg[s][1] = 0.f; }

    float4 xwp[4][2];
    auto pf_xw = [&](int t) {
#pragma unroll
        for (int s = 0; s < 4; ++s) {
            int b = m0 + rw + s * 32;
            size_t base = ((size_t)t * 256 + b) * 1024 + h0 + un;
            float2 vi = *(const float2*)(g_xwi + base);
            float2 vf = *(const float2*)(g_xwf + base);
            float2 vg = *(const float2*)(g_xwg + base);
            float2 vo = *(const float2*)(g_xwo + base);
            xwp[s][0] = make_float4(vi.x, vf.x, vg.x, vo.x);
            xwp[s][1] = make_float4(vi.y, vf.y, vg.y, vo.y);
        }
    };
    pf_xw(0);

    for (int t = 0; t < 512; ++t) {
        const __half* hin = g_h + (size_t)(t & 1) * 262144;

        auto issueR = [&](int j) {
            __half* dst = hs + (j % 3) * (128 * 72);
            const __half* src = hin + (size_t)m0 * 1024 + j * 64;
#pragma unroll
            for (int q = 0; q < 4; ++q) {
                int i = tid + q * 256;      // 0..1023
                int r = i >> 3, v = i & 7;
                cpa16(dst + r * 72 + v * 8, src + (size_t)r * 1024 + v * 8);
            }
            cpcommit();
        };

        float acc[2][4][4];
#pragma unroll
        for (int a = 0; a < 2; ++a)
#pragma unroll
            for (int b = 0; b < 4; ++b)
#pragma unroll
                for (int c = 0; c < 4; ++c) acc[a][b][c] = 0.f;

        issueR(0); issueR(1);

        for (int kc = 0; kc < 16; ++kc) {
            if (kc < 15) cpwait<1>();      // chunk kc complete
            else         cpwait<0>();
            __syncthreads();               // all warps done with stage (kc-1)%3
            if (kc + 2 < 16) issueR(kc + 2);   // writes stage (kc-1)%3 — safe
            const __half* hb = hs + (kc % 3) * (128 * 72);
#pragma unroll
            for (int k16 = 0; k16 < 4; ++k16) {
                const int kk = kc * 64 + k16 * 16;    // offset into full-K Ws
                const int hk = k16 * 16;              // offset into 64-wide hs
                unsigned af[2][4], bf[4][2];
#pragma unroll
                for (int ma = 0; ma < 2; ++ma)
                    ldmx4(af[ma][0], af[ma][1], af[ma][2], af[ma][3],
                          hb + (wm * 32 + ma * 16 + (lane & 15)) * 72
                             + hk + (lane >> 4) * 8);
#pragma unroll
                for (int pp = 0; pp < 2; ++pp) {
                    unsigned d0, d1, d2, d3;
                    ldmx4(d0, d1, d2, d3,
                          Ws + (wn * 32 + pp * 16 + ((lane >> 3) & 1) * 8
                                + (lane & 7)) * 1032 + kk + (lane >> 4) * 8);
                    bf[pp * 2 + 0][0] = d0; bf[pp * 2 + 1][0] = d1;
                    bf[pp * 2 + 0][1] = d2; bf[pp * 2 + 1][1] = d3;
                }
#pragma unroll
                for (int ma = 0; ma < 2; ++ma)
#pragma unroll
                    for (int na = 0; na < 4; ++na)
                        mma16816(acc[ma][na], af[ma], bf[na]);
            }
        }

        // spill z to smem — zs is dedicated and each warp's tile exclusive:
        // no sync needed between last mma and the spill
#pragma unroll
        for (int ma = 0; ma < 2; ++ma)
#pragma unroll
            for (int na = 0; na < 4; ++na) {
                int m = wm * 32 + ma * 16 + (lane >> 2);
                int n = wn * 32 + na * 8 + ((lane & 3) << 1);
                zs[m * 68 + n]           = acc[ma][na][0];
                zs[m * 68 + n + 1]       = acc[ma][na][1];
                zs[(m + 8) * 68 + n]     = acc[ma][na][2];
                zs[(m + 8) * 68 + n + 1] = acc[ma][na][3];
            }
        __syncthreads();

        // pointwise: 2 units x 4 row-groups per thread, all fp32
        __half* hout = g_h + (size_t)((t + 1) & 1) * 262144 + h0 + un;
#pragma unroll
        for (int s = 0; s < 4; ++s) {
            int r = rw + s * 32;
            int b = m0 + r;
            float2 z_i = *(float2*)&zs[r * 68 +  0 + un];
            float2 z_f = *(float2*)&zs[r * 68 + 16 + un];
            float2 z_g = *(float2*)&zs[r * 68 + 32 + un];
            float2 z_o = *(float2*)&zs[r * 68 + 48 + un];
            float i0 = fsig(z_i.x + xwp[s][0].x), i1 = fsig(z_i.y + xwp[s][1].x);
            float f0 = fsig(z_f.x + xwp[s][0].y), f1 = fsig(z_f.y + xwp[s][1].y);
            float gg0 = ftanh(z_g.x + xwp[s][0].z), gg1 = ftanh(z_g.y + xwp[s][1].z);
            float o0 = fsig(z_o.x + xwp[s][0].w), o1 = fsig(z_o.y + xwp[s][1].w);
            float c0 = f0 * creg[s][0] + i0 * gg0;
            float c1 = f1 * creg[s][1] + i1 * gg1;
            creg[s][0] = c0; creg[s][1] = c1;
            float hn0 = o0 * ftanh(c0);
            float hn1 = o1 * ftanh(c1);
            *(__half2*)(hout + (size_t)b * 1024) = __floats2half2_rn(hn0, hn1);
            if (t == 511)
                *(float2*)(g_hT + (size_t)b * 1024 + h0 + un) =
                    make_float2(hn0, hn1);
        }

        // global grid barrier (monotonic counter; 128 CTAs all co-resident)
        if (t < 511) {
            pf_xw(t + 1);          // hide xW DRAM latency under the barrier
            __syncthreads();
            if (tid == 0) {
                __threadfence();
                atomicAdd(&g_bar, 1u);
                unsigned target = 128u * (unsigned)(t + 1);
                volatile unsigned* bp = &g_bar;
                while (*bp < target) { }
                __threadfence();
            }
            __syncthreads();
        }
    }
}

// ------------------------------ phase C: FC --------------------------------
__global__ __launch_bounds__(256) void fc_kernel(const float* __restrict__ Wfc,
                                                 const float* __restrict__ bfc,
                                                 float* __restrict__ out) {
    __shared__ float As[16][17];
    __shared__ float Bs[16][17];
    const int tx = threadIdx.x, ty = threadIdx.y;
    const int row = blockIdx.y * 16 + ty;   // batch
    const int col = blockIdx.x * 16 + tx;   // out unit
    float acc = 0.f;
    for (int k0 = 0; k0 < 1024; k0 += 16) {
        As[ty][tx] = g_hT[(size_t)row * 1024 + k0 + tx];
        Bs[ty][tx] = Wfc[(size_t)(blockIdx.x * 16 + ty) * 1024 + k0 + tx];
        __syncthreads();
#pragma unroll
        for (int k = 0; k < 16; ++k) acc += As[ty][k] * Bs[tx][k];
        __syncthreads();
    }
    out[(size_t)row * 512 + col] = acc + bfc[col];
}

// ------------------------------- launcher ----------------------------------
extern "C" void kernel_launch(void* const* d_in, const int* in_sizes, int n_in,
                              void* d_out, int out_size) {
    const float* x   = (const float*)d_in[0];
    const float* Wih = (const float*)d_in[1];
    const float* Whh = (const float*)d_in[2];
    const float* bih = (const float*)d_in[3];
    const float* bhh = (const float*)d_in[4];
    const float* Wfc = (const float*)d_in[5];
    const float* bfc = (const float*)d_in[6];

    cudaFuncSetAttribute(xproj_kernel,
                         cudaFuncAttributeMaxDynamicSharedMemorySize, XP_SMEM);
    cudaFuncSetAttribute(lstm_rec_kernel,
                         cudaFuncAttributeMaxDynamicSharedMemorySize, REC_SMEM);

    dummy_kernel<<<1, 1>>>();   // launch-slot shim: puts rec at ncu's -s 5
    prep_kernel<<<4096, 256>>>(x, Wih, Whh, bih, bhh);
    xproj_kernel<<<dim3(32, 1024), 256, XP_SMEM>>>();
    lstm_rec_kernel<<<128, 256, REC_SMEM>>>();
    fc_kernel<<<dim3(32, 16), dim3(16, 16)>>>(Wfc, bfc, (float*)d_out);
}

// round 15
// speedup vs baseline: 1.0711x; 1.0711x over previous
#include <cuda_runtime.h>
#include <cuda_fp16.h>
#include <cstdint>
#include <cstddef>

// ---------------------------------------------------------------------------
// LSTM: x[256,512,512] -> LSTM(H=1024), last hidden -> FC(512). out fp32.
// dummy (ncu slot shim) -> prep -> xproj (R7-proven 128x128)
//   -> persistent recurrence: 512 threads/CTA (16 warps — latency hiding; ncu
//      showed occ 12.5%, issue 23%, tensor 23% with 8 warps), warp tile 32x16,
//      W_hh smem-stationary, 2-stage cp.async ring, c in regs, xW prefetch
//   -> fp32 FC
// tcgen05 unavailable: harness compiles PTX at compute_103 (no 'a' features).
// ---------------------------------------------------------------------------

#define DEVFN __device__ __forceinline__

// ------------------------- static device scratch ---------------------------
__device__ __half  g_x[67108864];        // x fp16 [b*512+t][512]
__device__ __half  g_Wih[2097152];       // W_ih fp16 [4096][512]
__device__ __half  g_Whh[4194304];       // W_hh fp16 [4096][1024]
__device__ float   g_bias[4096];         // b_ih + b_hh
__device__ float   g_xwi[134217728];     // per-gate xW fp32 [t][b][1024]
__device__ float   g_xwf[134217728];
__device__ float   g_xwg[134217728];
__device__ float   g_xwo[134217728];
__device__ __half  g_h[2 * 262144];      // double-buffered hidden fp16 [b][1024]
__device__ float   g_hT[262144];         // final hidden fp32
__device__ unsigned g_bar;               // grid barrier (monotonic)

// ------------------------------ helpers ------------------------------------
DEVFN void ldmx4(unsigned &r0, unsigned &r1, unsigned &r2, unsigned &r3,
                 const void* p) {
    unsigned a = (unsigned)__cvta_generic_to_shared(p);
    asm volatile("ldmatrix.sync.aligned.m8n8.x4.shared.b16 {%0,%1,%2,%3}, [%4];"
                 : "=r"(r0), "=r"(r1), "=r"(r2), "=r"(r3) : "r"(a));
}

DEVFN void mma16816(float* c, const unsigned* a, const unsigned* b) {
    asm volatile(
        "mma.sync.aligned.m16n8k16.row.col.f32.f16.f16.f32 "
        "{%0,%1,%2,%3}, {%4,%5,%6,%7}, {%8,%9}, {%0,%1,%2,%3};"
        : "+f"(c[0]), "+f"(c[1]), "+f"(c[2]), "+f"(c[3])
        : "r"(a[0]), "r"(a[1]), "r"(a[2]), "r"(a[3]), "r"(b[0]), "r"(b[1]));
}

// cp.async 16B, L2-only (.cg) — required for cross-SM h coherence
DEVFN void cpa16(void* smem, const void* gmem) {
    unsigned a = (unsigned)__cvta_generic_to_shared(smem);
    asm volatile("cp.async.cg.shared.global [%0], [%1], 16;" :: "r"(a), "l"(gmem));
}
DEVFN void cpcommit() { asm volatile("cp.async.commit_group;"); }
template <int N> DEVFN void cpwait() {
    asm volatile("cp.async.wait_group %0;" :: "n"(N));
}

DEVFN float fsig(float x)  { return 1.f / (1.f + __expf(-x)); }
DEVFN float ftanh(float x) { return 1.f - 2.f / (__expf(2.f * x) + 1.f); }

// ------------------------------ dummy kernel -------------------------------
// Launch-slot shim: keeps lstm_rec_kernel at the harness's ncu capture slot.
__global__ void dummy_kernel() {}

// ------------------------------- prep kernel -------------------------------
__global__ void prep_kernel(const float* __restrict__ x,
                            const float* __restrict__ Wih,
                            const float* __restrict__ Whh,
                            const float* __restrict__ bih,
                            const float* __restrict__ bhh) {
    size_t i0 = (size_t)blockIdx.x * blockDim.x + threadIdx.x;
    size_t stride = (size_t)gridDim.x * blockDim.x;
    for (size_t i = i0; i < 33554432u; i += stride) {
        float2 v = ((const float2*)x)[i];
        ((__half2*)g_x)[i] = __floats2half2_rn(v.x, v.y);
    }
    for (size_t i = i0; i < 1048576u; i += stride) {
        float2 v = ((const float2*)Wih)[i];
        ((__half2*)g_Wih)[i] = __floats2half2_rn(v.x, v.y);
    }
    for (size_t i = i0; i < 2097152u; i += stride) {
        float2 v = ((const float2*)Whh)[i];
        ((__half2*)g_Whh)[i] = __floats2half2_rn(v.x, v.y);
    }
    for (size_t i = i0; i < 4096u; i += stride) g_bias[i] = bih[i] + bhh[i];
    __half2 z2 = __float2half2_rn(0.f);
    for (size_t i = i0; i < 262144u; i += stride)
        ((__half2*)g_h)[i] = z2;   // zero both 256x1024 fp16 h buffers
    if (i0 == 0) g_bar = 0u;
}

// ------------------------- phase A: x @ W_ih^T (R7-proven) -----------------
// M=131072 (b*512+t), K=512, N=4096. CTA tile 128x128, 8 warps (2m x 4n),
// warp tile 64x32. 2-stage cp.async pipeline over 8 K-chunks of 64.
#define XP_SMEM (2 * 128 * 72 * 2 * 2)
__global__ __launch_bounds__(256) void xproj_kernel() {
    extern __shared__ __align__(16) unsigned char xsm[];
    __half* xs = (__half*)xsm;                       // [2][128][72]
    __half* ws = (__half*)(xsm + 2 * 128 * 72 * 2);  // [2][128][72]
    const int tid = threadIdx.x, lane = tid & 31, warp = tid >> 5;
    const int n0 = blockIdx.x * 128, m0 = blockIdx.y * 128;
    const int wm = warp >> 2, wn = warp & 3;

    float acc[4][4][4];
#pragma unroll
    for (int a = 0; a < 4; ++a)
#pragma unroll
        for (int b = 0; b < 4; ++b)
#pragma unroll
            for (int c = 0; c < 4; ++c) acc[a][b][c] = 0.f;

    const __half* xbase = g_x + (size_t)m0 * 512;
    const __half* wbase = g_Wih + (size_t)n0 * 512;

    auto issue = [&](int kc) {
        __half* xd = xs + (kc & 1) * 9216;
        __half* wd = ws + (kc & 1) * 9216;
        const __half* xsrc = xbase + kc * 64;
        const __half* wsrc = wbase + kc * 64;
#pragma unroll
        for (int q = 0; q < 4; ++q) {
            int i = tid + q * 256;          // 0..1023
            int r = i >> 3, v = i & 7;
            cpa16(xd + r * 72 + v * 8, xsrc + (size_t)r * 512 + v * 8);
            cpa16(wd + r * 72 + v * 8, wsrc + (size_t)r * 512 + v * 8);
        }
    };

    issue(0); cpcommit();
    for (int kc = 0; kc < 8; ++kc) {
        if (kc < 7) { issue(kc + 1); cpcommit(); cpwait<1>(); }
        else        { cpwait<0>(); }
        __syncthreads();
        const __half* xb = xs + (kc & 1) * 9216;
        const __half* wb = ws + (kc & 1) * 9216;
#pragma unroll
        for (int k16 = 0; k16 < 4; ++k16) {
            const int kk = k16 * 16;
            unsigned af[4][4], bf[4][2];
#pragma unroll
            for (int ma = 0; ma < 4; ++ma)
                ldmx4(af[ma][0], af[ma][1], af[ma][2], af[ma][3],
                      xb + (wm * 64 + ma * 16 + (lane & 15)) * 72
                         + kk + (lane >> 4) * 8);
#pragma unroll
            for (int pp = 0; pp < 2; ++pp) {
                unsigned d0, d1, d2, d3;
                ldmx4(d0, d1, d2, d3,
                      wb + (wn * 32 + pp * 16 + ((lane >> 3) & 1) * 8
                            + (lane & 7)) * 72 + kk + (lane >> 4) * 8);
                bf[pp * 2 + 0][0] = d0; bf[pp * 2 + 1][0] = d1;
                bf[pp * 2 + 0][1] = d2; bf[pp * 2 + 1][1] = d3;
            }
#pragma unroll
            for (int ma = 0; ma < 4; ++ma)
#pragma unroll
                for (int na = 0; na < 4; ++na)
                    mma16816(acc[ma][na], af[ma], bf[na]);
        }
        __syncthreads();
    }

    // store fp32 xW with bias, per-gate [t][b][unit]
    const int gate = n0 >> 10;
    float* xw = (gate == 0) ? g_xwi : (gate == 1) ? g_xwf
              : (gate == 2) ? g_xwg : g_xwo;
    const int nu0 = n0 & 1023;
#pragma unroll
    for (int ma = 0; ma < 4; ++ma)
#pragma unroll
        for (int na = 0; na < 4; ++na) {
            int m  = m0 + wm * 64 + ma * 16 + (lane >> 2);
            int nu = nu0 + wn * 32 + na * 8 + ((lane & 3) << 1);
            int bb = m >> 9, tt = m & 511;
            float bs0 = g_bias[(gate << 10) + nu];
            float bs1 = g_bias[(gate << 10) + nu + 1];
            size_t o0 = ((size_t)tt * 256 + bb) * 1024 + nu;
            *(float2*)(xw + o0) =
                make_float2(acc[ma][na][0] + bs0, acc[ma][na][1] + bs1);
            size_t o1 = ((size_t)(tt + 8) * 256 + bb) * 1024 + nu;
            *(float2*)(xw + o1) =
                make_float2(acc[ma][na][2] + bs0, acc[ma][na][3] + bs1);
        }
}

// --------------------- phase B: persistent recurrence ----------------------
// 128 CTAs = 2 m-tiles(128 batch rows) x 64 n-tiles(16 units = 64 gate cols).
// 512 threads / 16 warps (4m x 4n grid of 32x16 warp tiles) for latency
// hiding. Ws [64][1032] fp16 stationary; hs [2][128][72] ring; zs [128][68].
#define REC_SMEM (64 * 1032 * 2 + 2 * 128 * 72 * 2 + 128 * 68 * 4)
__global__ __launch_bounds__(512, 1) void lstm_rec_kernel() {
    extern __shared__ __align__(16) unsigned char smem_raw[];
    __half* Ws = (__half*)smem_raw;                              // [64][1032]
    __half* hs = (__half*)(smem_raw + 64 * 1032 * 2);            // [2][128][72]
    float*  zs = (float*)(smem_raw + 64 * 1032 * 2 + 2 * 128 * 72 * 2);

    const int tid = threadIdx.x, lane = tid & 31, warp = tid >> 5;
    const int nt = blockIdx.x & 63, mt = blockIdx.x >> 6;
    const int h0 = nt * 16, m0 = mt * 128;
    const int wm = warp >> 2, wn = warp & 3;   // warp tile 32m x 16n

    // load W_hh slice: smem row r <-> gate (r>>4), unit h0+(r&15); full K=1024
    for (int i = tid; i < 8192; i += 512) {
        int r = i >> 7, v = i & 127;
        int gr = ((r >> 4) << 10) + h0 + (r & 15);
        *(uint4*)(Ws + r * 1032 + v * 8) =
            *(const uint4*)(g_Whh + (size_t)gr * 1024 + v * 8);
    }

    const int un = (tid & 7) * 2;   // 2 adjacent units per thread
    const int rw = tid >> 3;        // row group 0..63
    float creg[2][2];
#pragma unroll
    for (int s = 0; s < 2; ++s) { creg[s][0] = 0.f; creg[s][1] = 0.f; }

    float4 xwp[2][2];
    auto pf_xw = [&](int t) {
#pragma unroll
        for (int s = 0; s < 2; ++s) {
            int b = m0 + rw + s * 64;
            size_t base = ((size_t)t * 256 + b) * 1024 + h0 + un;
            float2 vi = *(const float2*)(g_xwi + base);
            float2 vf = *(const float2*)(g_xwf + base);
            float2 vg = *(const float2*)(g_xwg + base);
            float2 vo = *(const float2*)(g_xwo + base);
            xwp[s][0] = make_float4(vi.x, vf.x, vg.x, vo.x);
            xwp[s][1] = make_float4(vi.y, vf.y, vg.y, vo.y);
        }
    };
    pf_xw(0);

    for (int t = 0; t < 512; ++t) {
        const __half* hin = g_h + (size_t)(t & 1) * 262144;

        auto issueR = [&](int j) {
            __half* dst = hs + (j & 1) * (128 * 72);
            const __half* src = hin + (size_t)m0 * 1024 + j * 64;
#pragma unroll
            for (int q = 0; q < 2; ++q) {
                int i = tid + q * 512;      // 0..1023
                int r = i >> 3, v = i & 7;
                cpa16(dst + r * 72 + v * 8, src + (size_t)r * 1024 + v * 8);
            }
        };

        float acc[2][2][4];
#pragma unroll
        for (int a = 0; a < 2; ++a)
#pragma unroll
            for (int b = 0; b < 2; ++b)
#pragma unroll
                for (int c = 0; c < 4; ++c) acc[a][b][c] = 0.f;

        issueR(0); cpcommit();
        for (int kc = 0; kc < 16; ++kc) {
            if (kc < 15) { issueR(kc + 1); cpcommit(); cpwait<1>(); }
            else         { cpwait<0>(); }
            __syncthreads();
            const __half* hb = hs + (kc & 1) * (128 * 72);
#pragma unroll
            for (int k16 = 0; k16 < 4; ++k16) {
                const int kk = kc * 64 + k16 * 16;    // offset into full-K Ws
                const int hk = k16 * 16;              // offset into 64-wide hs
                unsigned af[2][4], bf[2][2];
#pragma unroll
                for (int ma = 0; ma < 2; ++ma)
                    ldmx4(af[ma][0], af[ma][1], af[ma][2], af[ma][3],
                          hb + (wm * 32 + ma * 16 + (lane & 15)) * 72
                             + hk + (lane >> 4) * 8);
                {
                    unsigned d0, d1, d2, d3;
                    ldmx4(d0, d1, d2, d3,
                          Ws + (wn * 16 + ((lane >> 3) & 1) * 8
                                + (lane & 7)) * 1032 + kk + (lane >> 4) * 8);
                    bf[0][0] = d0; bf[1][0] = d1;
                    bf[0][1] = d2; bf[1][1] = d3;
                }
#pragma unroll
                for (int ma = 0; ma < 2; ++ma)
#pragma unroll
                    for (int na = 0; na < 2; ++na)
                        mma16816(acc[ma][na], af[ma], bf[na]);
            }
            __syncthreads();
        }

        // spill z to smem (per-warp exclusive 32x16 tiles)
#pragma unroll
        for (int ma = 0; ma < 2; ++ma)
#pragma unroll
            for (int na = 0; na < 2; ++na) {
                int m = wm * 32 + ma * 16 + (lane >> 2);
                int n = wn * 16 + na * 8 + ((lane & 3) << 1);
                zs[m * 68 + n]           = acc[ma][na][0];
                zs[m * 68 + n + 1]       = acc[ma][na][1];
                zs[(m + 8) * 68 + n]     = acc[ma][na][2];
                zs[(m + 8) * 68 + n + 1] = acc[ma][na][3];
            }
        __syncthreads();

        // pointwise: 2 units x 2 row-groups per thread, all fp32
        __half* hout = g_h + (size_t)((t + 1) & 1) * 262144 + h0 + un;
#pragma unroll
        for (int s = 0; s < 2; ++s) {
            int r = rw + s * 64;
            int b = m0 + r;
            float2 z_i = *(float2*)&zs[r * 68 +  0 + un];
            float2 z_f = *(float2*)&zs[r * 68 + 16 + un];
            float2 z_g = *(float2*)&zs[r * 68 + 32 + un];
            float2 z_o = *(float2*)&zs[r * 68 + 48 + un];
            float i0 = fsig(z_i.x + xwp[s][0].x), i1 = fsig(z_i.y + xwp[s][1].x);
            float f0 = fsig(z_f.x + xwp[s][0].y), f1 = fsig(z_f.y + xwp[s][1].y);
            float gg0 = ftanh(z_g.x + xwp[s][0].z), gg1 = ftanh(z_g.y + xwp[s][1].z);
            float o0 = fsig(z_o.x + xwp[s][0].w), o1 = fsig(z_o.y + xwp[s][1].w);
            float c0 = f0 * creg[s][0] + i0 * gg0;
            float c1 = f1 * creg[s][1] + i1 * gg1;
            creg[s][0] = c0; creg[s][1] = c1;
            float hn0 = o0 * ftanh(c0);
            float hn1 = o1 * ftanh(c1);
            *(__half2*)(hout + (size_t)b * 1024) = __floats2half2_rn(hn0, hn1);
            if (t == 511)
                *(float2*)(g_hT + (size_t)b * 1024 + h0 + un) =
                    make_float2(hn0, hn1);
        }

        // global grid barrier (monotonic counter; 128 CTAs all co-resident)
        if (t < 511) {
            pf_xw(t + 1);          // hide xW DRAM latency under the barrier
            __syncthreads();
            if (tid == 0) {
                __threadfence();
                atomicAdd(&g_bar, 1u);
                unsigned target = 128u * (unsigned)(t + 1);
                volatile unsigned* bp = &g_bar;
                while (*bp < target) { }
                __threadfence();
            }
            __syncthreads();
        }
    }
}

// ------------------------------ phase C: FC --------------------------------
__global__ __launch_bounds__(256) void fc_kernel(const float* __restrict__ Wfc,
                                                 const float* __restrict__ bfc,
                                                 float* __restrict__ out) {
    __shared__ float As[16][17];
    __shared__ float Bs[16][17];
    const int tx = threadIdx.x, ty = threadIdx.y;
    const int row = blockIdx.y * 16 + ty;   // batch
    const int col = blockIdx.x * 16 + tx;   // out unit
    float acc = 0.f;
    for (int k0 = 0; k0 < 1024; k0 += 16) {
        As[ty][tx] = g_hT[(size_t)row * 1024 + k0 + tx];
        Bs[ty][tx] = Wfc[(size_t)(blockIdx.x * 16 + ty) * 1024 + k0 + tx];
        __syncthreads();
#pragma unroll
        for (int k = 0; k < 16; ++k) acc += As[ty][k] * Bs[tx][k];
        __syncthreads();
    }
    out[(size_t)row * 512 + col] = acc + bfc[col];
}

// ------------------------------- launcher ----------------------------------
extern "C" void kernel_launch(void* const* d_in, const int* in_sizes, int n_in,
                              void* d_out, int out_size) {
    const float* x   = (const float*)d_in[0];
    const float* Wih = (const float*)d_in[1];
    const float* Whh = (const float*)d_in[2];
    const float* bih = (const float*)d_in[3];
    const float* bhh = (const float*)d_in[4];
    const float* Wfc = (const float*)d_in[5];
    const float* bfc = (const float*)d_in[6];

    cudaFuncSetAttribute(xproj_kernel,
                         cudaFuncAttributeMaxDynamicSharedMemorySize, XP_SMEM);
    cudaFuncSetAttribute(lstm_rec_kernel,
                         cudaFuncAttributeMaxDynamicSharedMemorySize, REC_SMEM);

    dummy_kernel<<<1, 1>>>();   // launch-slot shim: keeps rec at ncu's -s 5
    prep_kernel<<<4096, 256>>>(x, Wih, Whh, bih, bhh);
    xproj_kernel<<<dim3(32, 1024), 256, XP_SMEM>>>();
    lstm_rec_kernel<<<128, 512, REC_SMEM>>>();
    fc_kernel<<<dim3(32, 16), dim3(16, 16)>>>(Wfc, bfc, (float*)d_out);
}

// round 16
// speedup vs baseline: 1.1094x; 1.0358x over previous
#include <cuda_runtime.h>
#include <cuda_fp16.h>
#include <cstdint>
#include <cstddef>

// ---------------------------------------------------------------------------
// LSTM: x[256,512,512] -> LSTM(H=1024), last hidden -> FC(512). out fp32.
// dummy (ncu slot shim) -> prep -> xproj (R7-proven 128x128)
//   -> persistent recurrence, WARP-SPECIALIZED: 512 thr = 8 compute warps
//      (32x32 tiles: 256B/mma smem traffic) + 8 loader warps (cp.async ring,
//      named-barrier full/empty handoff). W_hh smem-stationary, c in regs,
//      xW prefetch under the global barrier.
//   -> fp32 FC
// tcgen05 unavailable: harness compiles PTX at compute_103 (no 'a' features).
// ---------------------------------------------------------------------------

#define DEVFN __device__ __forceinline__

// ------------------------- static device scratch ---------------------------
__device__ __half  g_x[67108864];        // x fp16 [b*512+t][512]
__device__ __half  g_Wih[2097152];       // W_ih fp16 [4096][512]
__device__ __half  g_Whh[4194304];       // W_hh fp16 [4096][1024]
__device__ float   g_bias[4096];         // b_ih + b_hh
__device__ float   g_xwi[134217728];     // per-gate xW fp32 [t][b][1024]
__device__ float   g_xwf[134217728];
__device__ float   g_xwg[134217728];
__device__ float   g_xwo[134217728];
__device__ __half  g_h[2 * 262144];      // double-buffered hidden fp16 [b][1024]
__device__ float   g_hT[262144];         // final hidden fp32
__device__ unsigned g_bar;               // grid barrier (monotonic)

// ------------------------------ helpers ------------------------------------
DEVFN void ldmx4(unsigned &r0, unsigned &r1, unsigned &r2, unsigned &r3,
                 const void* p) {
    unsigned a = (unsigned)__cvta_generic_to_shared(p);
    asm volatile("ldmatrix.sync.aligned.m8n8.x4.shared.b16 {%0,%1,%2,%3}, [%4];"
                 : "=r"(r0), "=r"(r1), "=r"(r2), "=r"(r3) : "r"(a));
}

DEVFN void mma16816(float* c, const unsigned* a, const unsigned* b) {
    asm volatile(
        "mma.sync.aligned.m16n8k16.row.col.f32.f16.f16.f32 "
        "{%0,%1,%2,%3}, {%4,%5,%6,%7}, {%8,%9}, {%0,%1,%2,%3};"
        : "+f"(c[0]), "+f"(c[1]), "+f"(c[2]), "+f"(c[3])
        : "r"(a[0]), "r"(a[1]), "r"(a[2]), "r"(a[3]), "r"(b[0]), "r"(b[1]));
}

// cp.async 16B, L2-only (.cg) — required for cross-SM h coherence
DEVFN void cpa16(void* smem, const void* gmem) {
    unsigned a = (unsigned)__cvta_generic_to_shared(smem);
    asm volatile("cp.async.cg.shared.global [%0], [%1], 16;" :: "r"(a), "l"(gmem));
}
DEVFN void cpcommit() { asm volatile("cp.async.commit_group;"); }
template <int N> DEVFN void cpwait() {
    asm volatile("cp.async.wait_group %0;" :: "n"(N));
}

// named barriers (count = all 512 threads; arrivers don't block)
DEVFN void barsync(int id)   { asm volatile("bar.sync %0, 512;"   :: "r"(id) : "memory"); }
DEVFN void bararrive(int id) { asm volatile("bar.arrive %0, 512;" :: "r"(id) : "memory"); }
DEVFN void membar_cta()      { asm volatile("membar.cta;" ::: "memory"); }
#define BAR_FULL(s)  (1 + (s))
#define BAR_EMPTY(s) (3 + (s))

DEVFN float fsig(float x)  { return 1.f / (1.f + __expf(-x)); }
DEVFN float ftanh(float x) { return 1.f - 2.f / (__expf(2.f * x) + 1.f); }

// ------------------------------ dummy kernel -------------------------------
// Launch-slot shim: keeps lstm_rec_kernel at the harness's ncu capture slot.
__global__ void dummy_kernel() {}

// ------------------------------- prep kernel -------------------------------
__global__ void prep_kernel(const float* __restrict__ x,
                            const float* __restrict__ Wih,
                            const float* __restrict__ Whh,
                            const float* __restrict__ bih,
                            const float* __restrict__ bhh) {
    size_t i0 = (size_t)blockIdx.x * blockDim.x + threadIdx.x;
    size_t stride = (size_t)gridDim.x * blockDim.x;
    for (size_t i = i0; i < 33554432u; i += stride) {
        float2 v = ((const float2*)x)[i];
        ((__half2*)g_x)[i] = __floats2half2_rn(v.x, v.y);
    }
    for (size_t i = i0; i < 1048576u; i += stride) {
        float2 v = ((const float2*)Wih)[i];
        ((__half2*)g_Wih)[i] = __floats2half2_rn(v.x, v.y);
    }
    for (size_t i = i0; i < 2097152u; i += stride) {
        float2 v = ((const float2*)Whh)[i];
        ((__half2*)g_Whh)[i] = __floats2half2_rn(v.x, v.y);
    }
    for (size_t i = i0; i < 4096u; i += stride) g_bias[i] = bih[i] + bhh[i];
    __half2 z2 = __float2half2_rn(0.f);
    for (size_t i = i0; i < 262144u; i += stride)
        ((__half2*)g_h)[i] = z2;   // zero both 256x1024 fp16 h buffers
    if (i0 == 0) g_bar = 0u;
}

// ------------------------- phase A: x @ W_ih^T (R7-proven) -----------------
// M=131072 (b*512+t), K=512, N=4096. CTA tile 128x128, 8 warps (2m x 4n),
// warp tile 64x32. 2-stage cp.async pipeline over 8 K-chunks of 64.
#define XP_SMEM (2 * 128 * 72 * 2 * 2)
__global__ __launch_bounds__(256) void xproj_kernel() {
    extern __shared__ __align__(16) unsigned char xsm[];
    __half* xs = (__half*)xsm;                       // [2][128][72]
    __half* ws = (__half*)(xsm + 2 * 128 * 72 * 2);  // [2][128][72]
    const int tid = threadIdx.x, lane = tid & 31, warp = tid >> 5;
    const int n0 = blockIdx.x * 128, m0 = blockIdx.y * 128;
    const int wm = warp >> 2, wn = warp & 3;

    float acc[4][4][4];
#pragma unroll
    for (int a = 0; a < 4; ++a)
#pragma unroll
        for (int b = 0; b < 4; ++b)
#pragma unroll
            for (int c = 0; c < 4; ++c) acc[a][b][c] = 0.f;

    const __half* xbase = g_x + (size_t)m0 * 512;
    const __half* wbase = g_Wih + (size_t)n0 * 512;

    auto issue = [&](int kc) {
        __half* xd = xs + (kc & 1) * 9216;
        __half* wd = ws + (kc & 1) * 9216;
        const __half* xsrc = xbase + kc * 64;
        const __half* wsrc = wbase + kc * 64;
#pragma unroll
        for (int q = 0; q < 4; ++q) {
            int i = tid + q * 256;          // 0..1023
            int r = i >> 3, v = i & 7;
            cpa16(xd + r * 72 + v * 8, xsrc + (size_t)r * 512 + v * 8);
            cpa16(wd + r * 72 + v * 8, wsrc + (size_t)r * 512 + v * 8);
        }
    };

    issue(0); cpcommit();
    for (int kc = 0; kc < 8; ++kc) {
        if (kc < 7) { issue(kc + 1); cpcommit(); cpwait<1>(); }
        else        { cpwait<0>(); }
        __syncthreads();
        const __half* xb = xs + (kc & 1) * 9216;
        const __half* wb = ws + (kc & 1) * 9216;
#pragma unroll
        for (int k16 = 0; k16 < 4; ++k16) {
            const int kk = k16 * 16;
            unsigned af[4][4], bf[4][2];
#pragma unroll
            for (int ma = 0; ma < 4; ++ma)
                ldmx4(af[ma][0], af[ma][1], af[ma][2], af[ma][3],
                      xb + (wm * 64 + ma * 16 + (lane & 15)) * 72
                         + kk + (lane >> 4) * 8);
#pragma unroll
            for (int pp = 0; pp < 2; ++pp) {
                unsigned d0, d1, d2, d3;
                ldmx4(d0, d1, d2, d3,
                      wb + (wn * 32 + pp * 16 + ((lane >> 3) & 1) * 8
                            + (lane & 7)) * 72 + kk + (lane >> 4) * 8);
                bf[pp * 2 + 0][0] = d0; bf[pp * 2 + 1][0] = d1;
                bf[pp * 2 + 0][1] = d2; bf[pp * 2 + 1][1] = d3;
            }
#pragma unroll
            for (int ma = 0; ma < 4; ++ma)
#pragma unroll
                for (int na = 0; na < 4; ++na)
                    mma16816(acc[ma][na], af[ma], bf[na]);
        }
        __syncthreads();
    }

    // store fp32 xW with bias, per-gate [t][b][unit]
    const int gate = n0 >> 10;
    float* xw = (gate == 0) ? g_xwi : (gate == 1) ? g_xwf
              : (gate == 2) ? g_xwg : g_xwo;
    const int nu0 = n0 & 1023;
#pragma unroll
    for (int ma = 0; ma < 4; ++ma)
#pragma unroll
        for (int na = 0; na < 4; ++na) {
            int m  = m0 + wm * 64 + ma * 16 + (lane >> 2);
            int nu = nu0 + wn * 32 + na * 8 + ((lane & 3) << 1);
            int bb = m >> 9, tt = m & 511;
            float bs0 = g_bias[(gate << 10) + nu];
            float bs1 = g_bias[(gate << 10) + nu + 1];
            size_t o0 = ((size_t)tt * 256 + bb) * 1024 + nu;
            *(float2*)(xw + o0) =
                make_float2(acc[ma][na][0] + bs0, acc[ma][na][1] + bs1);
            size_t o1 = ((size_t)(tt + 8) * 256 + bb) * 1024 + nu;
            *(float2*)(xw + o1) =
                make_float2(acc[ma][na][2] + bs0, acc[ma][na][3] + bs1);
        }
}

// --------------------- phase B: persistent recurrence ----------------------
// 128 CTAs = 2 m-tiles(128 batch rows) x 64 n-tiles(16 units = 64 gate cols).
// 512 threads: warps 0-7 COMPUTE (32x32 tiles, 4m x 2n), warps 8-15 LOADERS
// (cp.async ring depth 2, membar + named-barrier handoff). Ws stationary.
#define REC_SMEM (64 * 1032 * 2 + 2 * 128 * 72 * 2 + 128 * 68 * 4)
__global__ __launch_bounds__(512, 1) void lstm_rec_kernel() {
    extern __shared__ __align__(16) unsigned char smem_raw[];
    __half* Ws = (__half*)smem_raw;                              // [64][1032]
    __half* hs = (__half*)(smem_raw + 64 * 1032 * 2);            // [2][128][72]
    float*  zs = (float*)(smem_raw + 64 * 1032 * 2 + 2 * 128 * 72 * 2);

    const int tid = threadIdx.x, lane = tid & 31, warp = tid >> 5;
    const int nt = blockIdx.x & 63, mt = blockIdx.x >> 6;
    const int h0 = nt * 16, m0 = mt * 128;
    const bool is_comp = (warp < 8);
    const int wm = warp >> 1, wn = warp & 1;   // compute warp tile 32m x 32n
    const int ltid = tid - 256;                // loader linear id 0..255

    // load W_hh slice with ALL 512 threads (row r: gate r>>4, unit h0+(r&15))
    for (int i = tid; i < 8192; i += 512) {
        int r = i >> 7, v = i & 127;
        int gr = ((r >> 4) << 10) + h0 + (r & 15);
        *(uint4*)(Ws + r * 1032 + v * 8) =
            *(const uint4*)(g_Whh + (size_t)gr * 1024 + v * 8);
    }
    __syncthreads();

    const int un = (tid & 7) * 2;   // 2 adjacent units per thread
    const int rw = tid >> 3;        // row group 0..63
    float creg[2][2];
#pragma unroll
    for (int s = 0; s < 2; ++s) { creg[s][0] = 0.f; creg[s][1] = 0.f; }

    float4 xwp[2][2];
    auto pf_xw = [&](int t) {
#pragma unroll
        for (int s = 0; s < 2; ++s) {
            int b = m0 + rw + s * 64;
            size_t base = ((size_t)t * 256 + b) * 1024 + h0 + un;
            float2 vi = *(const float2*)(g_xwi + base);
            float2 vf = *(const float2*)(g_xwf + base);
            float2 vg = *(const float2*)(g_xwg + base);
            float2 vo = *(const float2*)(g_xwo + base);
            xwp[s][0] = make_float4(vi.x, vf.x, vg.x, vo.x);
            xwp[s][1] = make_float4(vi.y, vf.y, vg.y, vo.y);
        }
    };
    pf_xw(0);

    // prime the empty barriers so loaders' first waits pass (once, t=0)
    if (is_comp) { bararrive(BAR_EMPTY(0)); bararrive(BAR_EMPTY(1)); }

    for (int t = 0; t < 512; ++t) {
        const __half* hin = g_h + (size_t)(t & 1) * 262144;

        if (!is_comp) {
            // ---------------- loader warps: fill the 2-stage ring ----------
            auto issueR = [&](int j) {
                __half* dst = hs + (j & 1) * (128 * 72);
                const __half* src = hin + (size_t)m0 * 1024 + j * 64;
#pragma unroll
                for (int q = 0; q < 4; ++q) {
                    int i = ltid + q * 256;      // 0..1023
                    int r = i >> 3, v = i & 7;
                    cpa16(dst + r * 72 + v * 8, src + (size_t)r * 1024 + v * 8);
                }
                cpcommit();
            };
            barsync(BAR_EMPTY(0)); issueR(0);
            barsync(BAR_EMPTY(1)); issueR(1);
            for (int kc = 0; kc < 16; ++kc) {
                if (kc < 15) cpwait<1>(); else cpwait<0>();   // chunk kc landed
                membar_cta();                                  // visible CTA-wide
                bararrive(BAR_FULL(kc & 1));
                if (kc + 2 < 16) { barsync(BAR_EMPTY(kc & 1)); issueR(kc + 2); }
            }
        } else {
            // ---------------- compute warps: 32x32 tiles, no load stalls ---
            float acc[2][4][4];
#pragma unroll
            for (int a = 0; a < 2; ++a)
#pragma unroll
                for (int b = 0; b < 4; ++b)
#pragma unroll
                    for (int c = 0; c < 4; ++c) acc[a][b][c] = 0.f;

            for (int kc = 0; kc < 16; ++kc) {
                barsync(BAR_FULL(kc & 1));       // chunk kc ready
                const __half* hb = hs + (kc & 1) * (128 * 72);
#pragma unroll
                for (int k16 = 0; k16 < 4; ++k16) {
                    const int kk = kc * 64 + k16 * 16;   // offset into full-K Ws
                    const int hk = k16 * 16;             // offset into 64-wide hs
                    unsigned af[2][4], bf[4][2];
#pragma unroll
                    for (int ma = 0; ma < 2; ++ma)
                        ldmx4(af[ma][0], af[ma][1], af[ma][2], af[ma][3],
                              hb + (wm * 32 + ma * 16 + (lane & 15)) * 72
                                 + hk + (lane >> 4) * 8);
#pragma unroll
                    for (int pp = 0; pp < 2; ++pp) {
                        unsigned d0, d1, d2, d3;
                        ldmx4(d0, d1, d2, d3,
                              Ws + (wn * 32 + pp * 16 + ((lane >> 3) & 1) * 8
                                    + (lane & 7)) * 1032 + kk + (lane >> 4) * 8);
                        bf[pp * 2 + 0][0] = d0; bf[pp * 2 + 1][0] = d1;
                        bf[pp * 2 + 0][1] = d2; bf[pp * 2 + 1][1] = d3;
                    }
#pragma unroll
                    for (int ma = 0; ma < 2; ++ma)
#pragma unroll
                        for (int na = 0; na < 4; ++na)
                            mma16816(acc[ma][na], af[ma], bf[na]);
                }
                bararrive(BAR_EMPTY(kc & 1));    // stage free for chunk kc+2
            }

            // spill z to dedicated zs (per-warp exclusive 32x32 tiles)
#pragma unroll
            for (int ma = 0; ma < 2; ++ma)
#pragma unroll
                for (int na = 0; na < 4; ++na) {
                    int m = wm * 32 + ma * 16 + (lane >> 2);
                    int n = wn * 32 + na * 8 + ((lane & 3) << 1);
                    zs[m * 68 + n]           = acc[ma][na][0];
                    zs[m * 68 + n + 1]       = acc[ma][na][1];
                    zs[(m + 8) * 68 + n]     = acc[ma][na][2];
                    zs[(m + 8) * 68 + n + 1] = acc[ma][na][3];
                }
        }
        __syncthreads();   // zs complete; loaders rejoin

        // pointwise: 2 units x 2 row-groups per thread, all 512 threads
        __half* hout = g_h + (size_t)((t + 1) & 1) * 262144 + h0 + un;
#pragma unroll
        for (int s = 0; s < 2; ++s) {
            int r = rw + s * 64;
            int b = m0 + r;
            float2 z_i = *(float2*)&zs[r * 68 +  0 + un];
            float2 z_f = *(float2*)&zs[r * 68 + 16 + un];
            float2 z_g = *(float2*)&zs[r * 68 + 32 + un];
            float2 z_o = *(float2*)&zs[r * 68 + 48 + un];
            float i0 = fsig(z_i.x + xwp[s][0].x), i1 = fsig(z_i.y + xwp[s][1].x);
            float f0 = fsig(z_f.x + xwp[s][0].y), f1 = fsig(z_f.y + xwp[s][1].y);
            float gg0 = ftanh(z_g.x + xwp[s][0].z), gg1 = ftanh(z_g.y + xwp[s][1].z);
            float o0 = fsig(z_o.x + xwp[s][0].w), o1 = fsig(z_o.y + xwp[s][1].w);
            float c0 = f0 * creg[s][0] + i0 * gg0;
            float c1 = f1 * creg[s][1] + i1 * gg1;
            creg[s][0] = c0; creg[s][1] = c1;
            float hn0 = o0 * ftanh(c0);
            float hn1 = o1 * ftanh(c1);
            *(__half2*)(hout + (size_t)b * 1024) = __floats2half2_rn(hn0, hn1);
            if (t == 511)
                *(float2*)(g_hT + (size_t)b * 1024 + h0 + un) =
                    make_float2(hn0, hn1);
        }

        // global grid barrier (monotonic counter; 128 CTAs all co-resident)
        if (t < 511) {
            pf_xw(t + 1);          // hide xW DRAM latency under the barrier
            __syncthreads();
            if (tid == 0) {
                __threadfence();
                atomicAdd(&g_bar, 1u);
                unsigned target = 128u * (unsigned)(t + 1);
                volatile unsigned* bp = &g_bar;
                while (*bp < target) { }
                __threadfence();
            }
            __syncthreads();
        }
    }
}

// ------------------------------ phase C: FC --------------------------------
__global__ __launch_bounds__(256) void fc_kernel(const float* __restrict__ Wfc,
                                                 const float* __restrict__ bfc,
                                                 float* __restrict__ out) {
    __shared__ float As[16][17];
    __shared__ float Bs[16][17];
    const int tx = threadIdx.x, ty = threadIdx.y;
    const int row = blockIdx.y * 16 + ty;   // batch
    const int col = blockIdx.x * 16 + tx;   // out unit
    float acc = 0.f;
    for (int k0 = 0; k0 < 1024; k0 += 16) {
        As[ty][tx] = g_hT[(size_t)row * 1024 + k0 + tx];
        Bs[ty][tx] = Wfc[(size_t)(blockIdx.x * 16 + ty) * 1024 + k0 + tx];
        __syncthreads();
#pragma unroll
        for (int k = 0; k < 16; ++k) acc += As[ty][k] * Bs[tx][k];
        __syncthreads();
    }
    out[(size_t)row * 512 + col] = acc + bfc[col];
}

// ------------------------------- launcher ----------------------------------
extern "C" void kernel_launch(void* const* d_in, const int* in_sizes, int n_in,
                              void* d_out, int out_size) {
    const float* x   = (const float*)d_in[0];
    const float* Wih = (const float*)d_in[1];
    const float* Whh = (const float*)d_in[2];
    const float* bih = (const float*)d_in[3];
    const float* bhh = (const float*)d_in[4];
    const float* Wfc = (const float*)d_in[5];
    const float* bfc = (const float*)d_in[6];

    cudaFuncSetAttribute(xproj_kernel,
                         cudaFuncAttributeMaxDynamicSharedMemorySize, XP_SMEM);
    cudaFuncSetAttribute(lstm_rec_kernel,
                         cudaFuncAttributeMaxDynamicSharedMemorySize, REC_SMEM);

    dummy_kernel<<<1, 1>>>();   // launch-slot shim: keeps rec at ncu's -s 5
    prep_kernel<<<4096, 256>>>(x, Wih, Whh, bih, bhh);
    xproj_kernel<<<dim3(32, 1024), 256, XP_SMEM>>>();
    lstm_rec_kernel<<<128, 512, REC_SMEM>>>();
    fc_kernel<<<dim3(32, 16), dim3(16, 16)>>>(Wfc, bfc, (float*)d_out);
}